// round 1
// baseline (speedup 1.0000x reference)
#include <cuda_runtime.h>

// Problem constants
#define Nn   32
#define Cc   256
#define Tt   64
#define Vv   25
#define Kk   3
#define Dd   256
#define KT   9
#define PADT 4
#define TV   1600     // Tt*Vv
#define COLS 51200    // Nn*Tt*Vv
#define KC   768      // Kk*Cc  (GCN contraction dim)
#define KD   2304     // KT*Dd  (TCN contraction dim)

// Scratch (module-load allocated; no runtime allocation)
__device__ float d_xA[(size_t)KC * COLS];   // [k*Cc+c][col]   157 MB
__device__ float d_y [(size_t)Dd * COLS];   // [d][col]         52 MB
__device__ float d_z [(size_t)Dd * COLS];   // [d][col]         52 MB
__device__ float d_W2t[KC * Dd];            // [kc][d]  = W_gcn[k,d,c]
__device__ float d_Wt2[KD * Dd];            // [dt*256+d'][d] = W_tcn[d,d',dt]
__device__ float d_bias2[Dd * Vv];          // Σ_k b_gcn[k,d]*colsumA[k,w]
__device__ float d_scale[Dd];
__device__ float d_shift[Dd];

// ---------------------------------------------------------------------------
// Prep: weight transposes + folded GCN bias term
// ---------------------------------------------------------------------------
__global__ void prep_kernel(const float* __restrict__ Wg,   // [K][D][C]
                            const float* __restrict__ bg,   // [K][D]
                            const float* __restrict__ Wt,   // [D][D][KT][1]
                            const float* __restrict__ A)    // [K][V][V]
{
    int idx = blockIdx.x * blockDim.x + threadIdx.x;
    if (idx < KC * Dd) {
        int d  = idx & 255;
        int kc = idx >> 8;
        int k  = kc >> 8;
        int c  = kc & 255;
        d_W2t[idx] = Wg[(k * Dd + d) * Cc + c];
    }
    if (idx < KD * Dd) {
        int d   = idx & 255;
        int kap = idx >> 8;
        int dt  = kap >> 8;
        int dp  = kap & 255;
        d_Wt2[idx] = Wt[(d * Dd + dp) * KT + dt];
    }
    if (idx < Dd * Vv) {
        int d = idx / Vv, w = idx % Vv;
        float acc = 0.f;
        for (int k = 0; k < Kk; k++) {
            float cs = 0.f;
            for (int v = 0; v < Vv; v++) cs += A[k * Vv * Vv + v * Vv + w];
            acc += bg[k * Dd + d] * cs;
        }
        d_bias2[idx] = acc;
    }
}

// ---------------------------------------------------------------------------
// Stage A: xA[k, c, n*1600 + t*25 + w] = sum_v x[n,c,t,v] * A[k,v,w]
// One thread per (n,c,t) row; A cached in shared.
// ---------------------------------------------------------------------------
__global__ void stageA_kernel(const float* __restrict__ x,
                              const float* __restrict__ A)
{
    __shared__ float As[Kk][Vv][Vv];
    for (int i = threadIdx.x; i < Kk * Vv * Vv; i += blockDim.x)
        ((float*)As)[i] = A[i];
    __syncthreads();

    int idx = blockIdx.x * blockDim.x + threadIdx.x;   // over N*C*T
    if (idx >= Nn * Cc * Tt) return;
    int t  = idx % Tt;
    int nc = idx / Tt;
    int c  = nc % Cc;
    int n  = nc / Cc;

    const float* xr = x + (size_t)idx * Vv;   // x[n][c][t][:]
    float xv[Vv];
#pragma unroll
    for (int v = 0; v < Vv; v++) xv[v] = xr[v];

    size_t colb = (size_t)n * TV + t * Vv;
#pragma unroll
    for (int k = 0; k < Kk; k++) {
        float* dst = d_xA + (size_t)(k * Cc + c) * COLS + colb;
#pragma unroll
        for (int w = 0; w < Vv; w++) {
            float acc = 0.f;
#pragma unroll
            for (int v = 0; v < Vv; v++) acc = fmaf(xv[v], As[k][v][w], acc);
            dst[w] = acc;
        }
    }
}

// ---------------------------------------------------------------------------
// Tiled SGEMM 128x128x8, 256 threads, 8x8 per thread.
// GATHER=false: y[d][col] = sum_kc W2t[kc][d]*xA[kc][col] + bias2[d][col%25]
// GATHER=true : z[d][col] = b_tcn[d] +
//               sum_{dt,d'} Wt2[dt*256+d'][d] * y[d'][col + (dt-4)*25]  (t-masked)
// ---------------------------------------------------------------------------
template <bool GATHER>
__global__ void __launch_bounds__(256, 2)
gemm_kernel(const float* __restrict__ btcn, int Kdim)
{
    const float* Aw = GATHER ? d_Wt2 : d_W2t;
    const float* Bm = GATHER ? d_y   : d_xA;
    float*       Cm = GATHER ? d_z   : d_y;

    __shared__ float As[8][128];
    __shared__ float Bs[8][128];
    __shared__ int   tcolS[128];

    const int tid = threadIdx.x;
    const int tx = tid & 15;          // 0..15  -> 8 cols each
    const int ty = tid >> 4;          // 0..15  -> 8 rows each
    const int colBase = blockIdx.x * 128;
    const int rowBase = blockIdx.y * 128;

    if (GATHER) {
        if (tid < 128) {
            int col = colBase + tid;
            tcolS[tid] = (col % TV) / Vv;
        }
    }
    __syncthreads();

    const int la_k = tid >> 5;        // 0..7
    const int la_m = (tid & 31) << 2; // 0,4,...,124

    float acc[8][8];
#pragma unroll
    for (int i = 0; i < 8; i++)
#pragma unroll
        for (int j = 0; j < 8; j++) acc[i][j] = 0.f;

    for (int k0 = 0; k0 < Kdim; k0 += 8) {
        // A tile
        float4 av = *(const float4*)(Aw + (size_t)(k0 + la_k) * Dd + rowBase + la_m);
        *(float4*)&As[la_k][la_m] = av;
        // B tile
        if (!GATHER) {
            float4 bv = *(const float4*)(Bm + (size_t)(k0 + la_k) * COLS + colBase + la_m);
            *(float4*)&Bs[la_k][la_m] = bv;
        } else {
            int kap = k0 + la_k;
            int dt  = kap >> 8;
            int dp  = kap & 255;
            int sh  = (dt - PADT) * Vv;
            const float* src = Bm + (size_t)dp * COLS + colBase + sh;
#pragma unroll
            for (int j = 0; j < 4; j++) {
                int ci = la_m + j;
                int tt = tcolS[ci] + dt - PADT;
                Bs[la_k][ci] = (tt >= 0 && tt < Tt) ? src[ci] : 0.f;
            }
        }
        __syncthreads();

#pragma unroll
        for (int kk = 0; kk < 8; kk++) {
            float a[8], b[8];
            *(float4*)(a)     = *(float4*)&As[kk][ty * 8];
            *(float4*)(a + 4) = *(float4*)&As[kk][ty * 8 + 4];
            *(float4*)(b)     = *(float4*)&Bs[kk][tx * 8];
            *(float4*)(b + 4) = *(float4*)&Bs[kk][tx * 8 + 4];
#pragma unroll
            for (int i = 0; i < 8; i++)
#pragma unroll
                for (int j = 0; j < 8; j++)
                    acc[i][j] = fmaf(a[i], b[j], acc[i][j]);
        }
        __syncthreads();
    }

    // Epilogue
#pragma unroll
    for (int i = 0; i < 8; i++) {
        int m = rowBase + ty * 8 + i;
        float bi = GATHER ? btcn[m] : 0.f;
        float* dst = Cm + (size_t)m * COLS + colBase + tx * 8;
#pragma unroll
        for (int j = 0; j < 8; j++) {
            float v = acc[i][j];
            if (GATHER) {
                v += bi;
            } else {
                int col = colBase + tx * 8 + j;
                v += d_bias2[m * Vv + (col % Vv)];
            }
            dst[j] = v;
        }
    }
}

// ---------------------------------------------------------------------------
// BN statistics: one block per channel d (deterministic reduction).
// Produces fused scale/shift: out = scale*z + shift
// ---------------------------------------------------------------------------
__global__ void bnstats_kernel(const float* __restrict__ gamma,
                               const float* __restrict__ beta)
{
    int d = blockIdx.x;
    const float* zr = d_z + (size_t)d * COLS;
    float s = 0.f, sq = 0.f;
    for (int i = threadIdx.x; i < COLS; i += 256) {
        float v = zr[i];
        s  += v;
        sq += v * v;
    }
    __shared__ float sh1[256], sh2[256];
    sh1[threadIdx.x] = s;
    sh2[threadIdx.x] = sq;
    __syncthreads();
    for (int o = 128; o > 0; o >>= 1) {
        if (threadIdx.x < o) {
            sh1[threadIdx.x] += sh1[threadIdx.x + o];
            sh2[threadIdx.x] += sh2[threadIdx.x + o];
        }
        __syncthreads();
    }
    if (threadIdx.x == 0) {
        float mean = sh1[0] * (1.0f / COLS);
        float var  = sh2[0] * (1.0f / COLS) - mean * mean;
        float r    = rsqrtf(var + 1e-5f);
        d_scale[d] = gamma[d] * r;
        d_shift[d] = beta[d] - gamma[d] * mean * r;
    }
}

// ---------------------------------------------------------------------------
// Finalize: BN apply + residual + ReLU, transpose [d][n,t,v] -> [n][d][t][v]
// ---------------------------------------------------------------------------
__global__ void finalize_kernel(const float* __restrict__ x,
                                float* __restrict__ out)
{
    int e = blockIdx.x * 256 + threadIdx.x;     // total = Nn*Dd*TV, exact multiple of 256
    int n = e / (Dd * TV);
    int r = e % (Dd * TV);
    int d = r / TV;
    int s = r % TV;
    float z = d_z[(size_t)d * COLS + n * TV + s];
    float v = fmaf(d_scale[d], z, d_shift[d]) + x[e];
    out[e] = fmaxf(v, 0.f);
}

// ---------------------------------------------------------------------------
extern "C" void kernel_launch(void* const* d_in, const int* in_sizes, int n_in,
                              void* d_out, int out_size)
{
    const float* x     = (const float*)d_in[0];
    const float* A     = (const float*)d_in[1];
    const float* W_gcn = (const float*)d_in[2];
    const float* b_gcn = (const float*)d_in[3];
    const float* W_tcn = (const float*)d_in[4];
    const float* b_tcn = (const float*)d_in[5];
    const float* gamma = (const float*)d_in[6];
    const float* beta  = (const float*)d_in[7];
    float* out = (float*)d_out;

    // 1. prep (transposes + folded bias)
    prep_kernel<<<(KD * Dd + 255) / 256, 256>>>(W_gcn, b_gcn, W_tcn, A);

    // 2. graph aggregation: xA = x * A[k]  (per k)
    stageA_kernel<<<(Nn * Cc * Tt + 255) / 256, 256>>>(x, A);

    // 3. GCN GEMM: y[256 x 51200] = W2t^T[256 x 768] * xA[768 x 51200] + bias2
    {
        dim3 grid(COLS / 128, Dd / 128);
        gemm_kernel<false><<<grid, 256>>>(nullptr, KC);
    }

    // 4. TCN implicit-im2col GEMM: z = Wt2^T * gather(y) + b_tcn
    {
        dim3 grid(COLS / 128, Dd / 128);
        gemm_kernel<true><<<grid, 256>>>(b_tcn, KD);
    }

    // 5. BN stats (deterministic, one block per channel)
    bnstats_kernel<<<Dd, 256>>>(gamma, beta);

    // 6. BN apply + residual + ReLU + layout transpose
    finalize_kernel<<<(Nn * Dd * TV) / 256, 256>>>(x, out);
}

// round 6
// speedup vs baseline: 2.5810x; 2.5810x over previous
#include <cuda_runtime.h>
#include <cuda_bf16.h>
#include <cstdint>

// Problem constants
#define Nn   32
#define Cc   256
#define Tt   64
#define Vv   25
#define Kk   3
#define Dd   256
#define KT   9
#define PADT 4
#define TV   1600     // Tt*Vv
#define COLS 51200    // Nn*Tt*Vv
#define KC   768      // GCN contraction dim
#define KD   2304     // TCN contraction dim
#define NCH1 24       // KC/32
#define NCH2 72       // KD/32

// per-chunk weight image: hi plane [128][40 u16] + lo plane -> 20480 bytes
#define IMGB      20480
#define PLANE_B   10240
#define ROWSTRIDE 80      // bytes per smem row (32 bf16 + 8 pad)

// ---------------------------------------------------------------------------
// Scratch (module-load allocated)
__device__ uint32_t d_xP[(size_t)KC * COLS];   // packed bf16 hi|lo<<16
__device__ uint32_t d_yP[(size_t)Dd * COLS];
__device__ float    d_z [(size_t)Dd * COLS];
__device__ char d_W1s[2 * NCH1 * IMGB];
__device__ char d_W2s[2 * NCH2 * IMGB];
__device__ float d_bias2[Dd * Vv];
__device__ float d_scale[Dd];
__device__ float d_shift[Dd];

// ---------------------------------------------------------------------------
__device__ __forceinline__ uint32_t smem_u32(const void* p) {
    uint32_t a;
    asm("{ .reg .u64 t; cvta.to.shared.u64 t, %1; cvt.u32.u64 %0, t; }"
        : "=r"(a) : "l"(p));
    return a;
}

#define LDSM4(r0, r1, r2, r3, addr) \
    asm volatile("ldmatrix.sync.aligned.m8n8.x4.shared.b16 {%0,%1,%2,%3}, [%4];" \
                 : "=r"(r0), "=r"(r1), "=r"(r2), "=r"(r3) : "r"(addr))

#define MMA16816(d, a, b) \
    asm volatile("mma.sync.aligned.m16n8k16.row.col.f32.bf16.bf16.f32 " \
                 "{%0,%1,%2,%3}, {%4,%5,%6,%7}, {%8,%9}, {%0,%1,%2,%3};" \
                 : "+f"((d)[0]), "+f"((d)[1]), "+f"((d)[2]), "+f"((d)[3]) \
                 : "r"((a)[0]), "r"((a)[1]), "r"((a)[2]), "r"((a)[3]), \
                   "r"((b)[0]), "r"((b)[1]))

__device__ __forceinline__ uint32_t f2pack(float v) {
    __nv_bfloat16 h = __float2bfloat16(v);
    __nv_bfloat16 l = __float2bfloat16(v - __bfloat162float(h));
    return (uint32_t)__bfloat16_as_ushort(h) |
           ((uint32_t)__bfloat16_as_ushort(l) << 16);
}

// ---------------------------------------------------------------------------
// Prep: build copy-ready hi/lo weight images + folded GCN bias
// ---------------------------------------------------------------------------
__global__ void prep_kernel(const float* __restrict__ Wg,   // [K][D][C]
                            const float* __restrict__ bg,   // [K][D]
                            const float* __restrict__ Wt,   // [D][D][KT]
                            const float* __restrict__ A)    // [K][V][V]
{
    int idx = blockIdx.x * blockDim.x + threadIdx.x;

    if (idx < 2 * NCH1 * 4096) {
        int e = idx & 4095, img = idx >> 12;
        int ch = img % NCH1, rb = img / NCH1;
        int row = e >> 5, kl = e & 31;
        int kc = ch * 32 + kl;
        int k = kc >> 8, c = kc & 255;
        int d = rb * 128 + row;
        float w = Wg[((size_t)(k * Dd + d)) * Cc + c];
        __nv_bfloat16 h = __float2bfloat16(w);
        __nv_bfloat16 l = __float2bfloat16(w - __bfloat162float(h));
        char* base = d_W1s + (size_t)(rb * NCH1 + ch) * IMGB;
        *(unsigned short*)(base + row * ROWSTRIDE + kl * 2)           = __bfloat16_as_ushort(h);
        *(unsigned short*)(base + PLANE_B + row * ROWSTRIDE + kl * 2) = __bfloat16_as_ushort(l);
    }
    if (idx < 2 * NCH2 * 4096) {
        int e = idx & 4095, img = idx >> 12;
        int ch = img % NCH2, rb = img / NCH2;
        int row = e >> 5, kl = e & 31;
        int kap = ch * 32 + kl;
        int dt = kap >> 8, dp = kap & 255;
        int d = rb * 128 + row;
        float w = Wt[((size_t)(d * Dd + dp)) * KT + dt];
        __nv_bfloat16 h = __float2bfloat16(w);
        __nv_bfloat16 l = __float2bfloat16(w - __bfloat162float(h));
        char* base = d_W2s + (size_t)(rb * NCH2 + ch) * IMGB;
        *(unsigned short*)(base + row * ROWSTRIDE + kl * 2)           = __bfloat16_as_ushort(h);
        *(unsigned short*)(base + PLANE_B + row * ROWSTRIDE + kl * 2) = __bfloat16_as_ushort(l);
    }
    if (idx < Dd * Vv) {
        int d = idx / Vv, w = idx % Vv;
        float acc = 0.f;
        for (int k = 0; k < Kk; k++) {
            float cs = 0.f;
            for (int v = 0; v < Vv; v++) cs += A[k * Vv * Vv + v * Vv + w];
            acc += bg[k * Dd + d] * cs;
        }
        d_bias2[idx] = acc;
    }
}

// ---------------------------------------------------------------------------
// Stage A: xP[kc][col] = packed-bf16( sum_v x[n,c,t,v] * A[k,v,w] )
// ---------------------------------------------------------------------------
__global__ void stageA_kernel(const float* __restrict__ x,
                              const float* __restrict__ A)
{
    __shared__ float As[Kk][Vv][Vv];
    for (int i = threadIdx.x; i < Kk * Vv * Vv; i += blockDim.x)
        ((float*)As)[i] = A[i];
    __syncthreads();

    int idx = blockIdx.x * blockDim.x + threadIdx.x;
    if (idx >= Nn * Cc * Tt) return;
    int t  = idx % Tt;
    int nc = idx / Tt;
    int c  = nc % Cc;
    int n  = nc / Cc;

    const float* xr = x + (size_t)idx * Vv;
    float xv[Vv];
#pragma unroll
    for (int v = 0; v < Vv; v++) xv[v] = xr[v];

    size_t colb = (size_t)n * TV + t * Vv;
#pragma unroll
    for (int k = 0; k < Kk; k++) {
        uint32_t* dst = d_xP + (size_t)(k * Cc + c) * COLS + colb;
#pragma unroll
        for (int w = 0; w < Vv; w++) {
            float acc = 0.f;
#pragma unroll
            for (int v = 0; v < Vv; v++) acc = fmaf(xv[v], As[k][v][w], acc);
            dst[w] = f2pack(acc);
        }
    }
}

// ---------------------------------------------------------------------------
// Split-bf16 warp-MMA GEMM.  Tile 128(M) x 128(N), K-chunk 32, 8 warps (2x4).
// smem stage: Ah | Al | Bh | Bl planes, each 128 rows x 80B (32 bf16 + pad).
// ---------------------------------------------------------------------------
#define STG_B  (4 * PLANE_B)          // 40960
#define OFF_AH 0
#define OFF_AL PLANE_B
#define OFF_BH (2 * PLANE_B)
#define OFF_BL (3 * PLANE_B)
#define SMEM_DYN (2 * STG_B + 512)    // + tcol table

template <bool GATHER>
__global__ void __launch_bounds__(256, 1)
mma_gemm(const float* __restrict__ btcn)
{
    constexpr int NCH = GATHER ? NCH2 : NCH1;
    const char* Wimg = GATHER ? d_W2s : d_W1s;
    const uint32_t* Bsrc = GATHER ? d_yP : d_xP;

    extern __shared__ char sm[];
    int* tcolS = (int*)(sm + 2 * STG_B);

    const int tid  = threadIdx.x;
    const int wid  = tid >> 5;
    const int lane = tid & 31;
    const int rowBase = blockIdx.x * 128;
    const int colBase = blockIdx.y * 128;

    const int nB   = tid & 127;   // B-fill column (0..127)
    const int half = tid >> 7;    // 0/1: which 16 k-rows

    if (GATHER && tid < 128) {
        int col = colBase + tid;
        tcolS[tid] = (col % TV) / Vv;
    }
    __syncthreads();

    // ---------------- fill helpers ----------------
    auto ldgA = [&](int ch, float4 a[5]) {
        const float4* src = (const float4*)(Wimg + (size_t)(blockIdx.x * NCH + ch) * IMGB);
#pragma unroll
        for (int r = 0; r < 5; r++) a[r] = src[tid + r * 256];
    };
    auto stsA = [&](char* stg, const float4 a[5]) {
        float4* dst = (float4*)stg;
#pragma unroll
        for (int r = 0; r < 5; r++) dst[tid + r * 256] = a[r];
    };
    auto ldgB = [&](int ch, uint32_t b[16]) {
        int k0row;
        long long srcCol;
        bool valid = true;
        if (!GATHER) {
            k0row = ch * 32;
            srcCol = colBase + nB;
        } else {
            int dt = ch >> 3;
            k0row = (ch & 7) * 32;
            int tt = tcolS[nB] + dt - PADT;
            valid = ((unsigned)tt < (unsigned)Tt);
            srcCol = (long long)(colBase + nB) + (long long)(dt - PADT) * Vv;
        }
        const uint32_t* src = Bsrc + ((long long)(k0row + half * 16)) * COLS + srcCol;
#pragma unroll
        for (int j = 0; j < 8; j++) {
            b[2 * j]     = valid ? src[(2 * j) * COLS]     : 0u;
            b[2 * j + 1] = valid ? src[(2 * j + 1) * COLS] : 0u;
        }
    };
    auto stsB = [&](char* stg, const uint32_t b[16]) {
        char* bh = stg + OFF_BH + nB * ROWSTRIDE + half * 32;
        char* bl = stg + OFF_BL + nB * ROWSTRIDE + half * 32;
#pragma unroll
        for (int j = 0; j < 8; j++) {
            uint32_t w0 = b[2 * j], w1 = b[2 * j + 1];
            *(uint32_t*)(bh + j * 4) = __byte_perm(w0, w1, 0x5410);  // hi pair
            *(uint32_t*)(bl + j * 4) = __byte_perm(w0, w1, 0x7632);  // lo pair
        }
    };

    // ---------------- accumulators ----------------
    float acc[4][4][4];
#pragma unroll
    for (int i = 0; i < 4; i++)
#pragma unroll
        for (int j = 0; j < 4; j++)
#pragma unroll
            for (int r = 0; r < 4; r++) acc[i][j][r] = 0.f;

    const int wm = wid >> 2;       // 0..1 -> 64 rows
    const int wn = wid & 3;        // 0..3 -> 32 cols

    const uint32_t smBase = smem_u32(sm);
    const int aRow = wm * 64 + ((lane >> 3) & 1) * 8 + (lane & 7);
    const int aCol = (lane >> 4) * 8;
    const int bRow = wn * 32 + ((lane >> 4) & 1) * 8 + (lane & 7);
    const int bCol = ((lane >> 3) & 1) * 8;

    // ---------------- prologue: fill buffer 0 ----------------
    {
        float4 a[5]; uint32_t b[16];
        ldgA(0, a); ldgB(0, b);
        stsA(sm, a); stsB(sm, b);
    }
    __syncthreads();

    float4 aReg[5]; uint32_t bReg[16];

    for (int i = 0; i < NCH; i++) {
        const uint32_t curS = smBase + (i & 1) * STG_B;

        if (i + 1 < NCH) { ldgA(i + 1, aReg); ldgB(i + 1, bReg); }

        // ---------------- compute chunk i ----------------
#pragma unroll
        for (int ks = 0; ks < 2; ks++) {
            uint32_t ah[4][4], al[4][4], bh[4][2], bl[4][2];
#pragma unroll
            for (int mf = 0; mf < 4; mf++) {
                uint32_t ad = curS + OFF_AH +
                              (aRow + mf * 16) * ROWSTRIDE + (aCol + ks * 16) * 2;
                LDSM4(ah[mf][0], ah[mf][1], ah[mf][2], ah[mf][3], ad);
                LDSM4(al[mf][0], al[mf][1], al[mf][2], al[mf][3], ad + PLANE_B);
            }
#pragma unroll
            for (int g = 0; g < 2; g++) {
                uint32_t bd = curS + OFF_BH +
                              (bRow + g * 16) * ROWSTRIDE + (bCol + ks * 16) * 2;
                uint32_t r0, r1, r2, r3;
                LDSM4(r0, r1, r2, r3, bd);
                bh[g * 2][0] = r0; bh[g * 2][1] = r1;
                bh[g * 2 + 1][0] = r2; bh[g * 2 + 1][1] = r3;
                LDSM4(r0, r1, r2, r3, bd + PLANE_B);
                bl[g * 2][0] = r0; bl[g * 2][1] = r1;
                bl[g * 2 + 1][0] = r2; bl[g * 2 + 1][1] = r3;
            }
#pragma unroll
            for (int mf = 0; mf < 4; mf++)
#pragma unroll
                for (int nf = 0; nf < 4; nf++) {
                    MMA16816(acc[mf][nf], ah[mf], bh[nf]);
                    MMA16816(acc[mf][nf], al[mf], bh[nf]);
                    MMA16816(acc[mf][nf], ah[mf], bl[nf]);
                }
        }

        if (i + 1 < NCH) {
            char* nxt = sm + ((i + 1) & 1) * STG_B;
            stsA(nxt, aReg); stsB(nxt, bReg);
        }
        __syncthreads();
    }

    // ---------------- epilogue ----------------
    const int mB = rowBase + wm * 64 + (lane >> 2);
    const int nB0 = colBase + wn * 32 + (lane & 3) * 2;
#pragma unroll
    for (int mf = 0; mf < 4; mf++) {
#pragma unroll
        for (int h = 0; h < 2; h++) {          // row halves (+0 / +8)
            int m = mB + mf * 16 + h * 8;
#pragma unroll
            for (int nf = 0; nf < 4; nf++) {
                int col = nB0 + nf * 8;
                float v0 = acc[mf][nf][2 * h];
                float v1 = acc[mf][nf][2 * h + 1];
                if (!GATHER) {
                    v0 += d_bias2[m * Vv + (col % Vv)];
                    v1 += d_bias2[m * Vv + ((col + 1) % Vv)];
                    uint2 pk = make_uint2(f2pack(v0), f2pack(v1));
                    *(uint2*)(d_yP + (size_t)m * COLS + col) = pk;
                } else {
                    float bi = btcn[m];
                    float2 f = make_float2(v0 + bi, v1 + bi);
                    *(float2*)(d_z + (size_t)m * COLS + col) = f;
                }
            }
        }
    }
}

// ---------------------------------------------------------------------------
// BN statistics (deterministic, one block per channel)
// ---------------------------------------------------------------------------
__global__ void bnstats_kernel(const float* __restrict__ gamma,
                               const float* __restrict__ beta)
{
    int d = blockIdx.x;
    const float* zr = d_z + (size_t)d * COLS;
    float s = 0.f, sq = 0.f;
    for (int i = threadIdx.x; i < COLS; i += 256) {
        float v = zr[i];
        s  += v;
        sq += v * v;
    }
    __shared__ float sh1[256], sh2[256];
    sh1[threadIdx.x] = s;
    sh2[threadIdx.x] = sq;
    __syncthreads();
    for (int o = 128; o > 0; o >>= 1) {
        if (threadIdx.x < o) {
            sh1[threadIdx.x] += sh1[threadIdx.x + o];
            sh2[threadIdx.x] += sh2[threadIdx.x + o];
        }
        __syncthreads();
    }
    if (threadIdx.x == 0) {
        float mean = sh1[0] * (1.0f / COLS);
        float var  = sh2[0] * (1.0f / COLS) - mean * mean;
        float r    = rsqrtf(var + 1e-5f);
        d_scale[d] = gamma[d] * r;
        d_shift[d] = beta[d] - gamma[d] * mean * r;
    }
}

// ---------------------------------------------------------------------------
// Finalize: BN apply + residual + ReLU, transpose [d][n,t,v] -> [n][d][t][v]
// ---------------------------------------------------------------------------
__global__ void finalize_kernel(const float* __restrict__ x,
                                float* __restrict__ out)
{
    int e = blockIdx.x * 256 + threadIdx.x;
    int n = e / (Dd * TV);
    int r = e % (Dd * TV);
    int d = r / TV;
    int s = r % TV;
    float z = d_z[(size_t)d * COLS + n * TV + s];
    float v = fmaf(d_scale[d], z, d_shift[d]) + x[e];
    out[e] = fmaxf(v, 0.f);
}

// ---------------------------------------------------------------------------
extern "C" void kernel_launch(void* const* d_in, const int* in_sizes, int n_in,
                              void* d_out, int out_size)
{
    const float* x     = (const float*)d_in[0];
    const float* A     = (const float*)d_in[1];
    const float* W_gcn = (const float*)d_in[2];
    const float* b_gcn = (const float*)d_in[3];
    const float* W_tcn = (const float*)d_in[4];
    const float* b_tcn = (const float*)d_in[5];
    const float* gamma = (const float*)d_in[6];
    const float* beta  = (const float*)d_in[7];
    float* out = (float*)d_out;

    cudaFuncSetAttribute(mma_gemm<false>, cudaFuncAttributeMaxDynamicSharedMemorySize, SMEM_DYN);
    cudaFuncSetAttribute(mma_gemm<true>,  cudaFuncAttributeMaxDynamicSharedMemorySize, SMEM_DYN);

    prep_kernel<<<(2 * NCH2 * 4096 + 255) / 256, 256>>>(W_gcn, b_gcn, W_tcn, A);
    stageA_kernel<<<(Nn * Cc * Tt + 255) / 256, 256>>>(x, A);

    mma_gemm<false><<<dim3(2, 400), 256, SMEM_DYN>>>(nullptr);
    mma_gemm<true><<<dim3(2, 400), 256, SMEM_DYN>>>(b_tcn);

    bnstats_kernel<<<Dd, 256>>>(gamma, beta);
    finalize_kernel<<<(Nn * Dd * TV) / 256, 256>>>(x, out);
}

// round 11
// speedup vs baseline: 2.6974x; 1.0451x over previous
#include <cuda_runtime.h>
#include <cuda_bf16.h>
#include <cstdint>

// Problem constants
#define Nn   32
#define Cc   256
#define Tt   64
#define Vv   25
#define Kk   3
#define Dd   256
#define KT   9
#define PADT 4
#define TV   1600     // Tt*Vv
#define COLS 51200    // Nn*Tt*Vv
#define KC   768      // GCN contraction dim
#define KD   2304     // TCN contraction dim
#define CHK  64       // K per chunk
#define NCH1 12       // KC/64
#define NCH2 36       // KD/64

// smem plane: 128 rows x 176B (64 bf16 = 128B + 48B pad; 44 words/row keeps
// both ldmatrix reads and sts writes conflict-free)
#define ROWSTRIDE 176
#define PLANE_B   (128 * ROWSTRIDE)   // 22528
#define IMGB      (2 * PLANE_B)       // hi+lo planes per chunk: 45056

// ---------------------------------------------------------------------------
// Scratch (module-load allocated)
__device__ uint32_t d_xP[(size_t)KC * COLS];   // packed bf16 hi|lo<<16
__device__ uint32_t d_yP[(size_t)Dd * COLS];
__device__ float    d_z [(size_t)Dd * COLS];
__device__ char d_W1s[2 * NCH1 * IMGB];
__device__ char d_W2s[2 * NCH2 * IMGB];
__device__ float d_bias2[Dd * Vv];
__device__ float d_scale[Dd];
__device__ float d_shift[Dd];

// ---------------------------------------------------------------------------
__device__ __forceinline__ uint32_t smem_u32(const void* p) {
    uint32_t a;
    asm("{ .reg .u64 t; cvta.to.shared.u64 t, %1; cvt.u32.u64 %0, t; }"
        : "=r"(a) : "l"(p));
    return a;
}

#define CP_ASYNC16(smaddr, gptr) \
    asm volatile("cp.async.cg.shared.global [%0], [%1], 16;" \
                 :: "r"(smaddr), "l"(gptr))
#define CP_COMMIT() asm volatile("cp.async.commit_group;")
#define CP_WAIT0()  asm volatile("cp.async.wait_group 0;" ::: "memory")

#define LDSM4(r0, r1, r2, r3, addr) \
    asm volatile("ldmatrix.sync.aligned.m8n8.x4.shared.b16 {%0,%1,%2,%3}, [%4];" \
                 : "=r"(r0), "=r"(r1), "=r"(r2), "=r"(r3) : "r"(addr))

#define MMA16816(d, a, b) \
    asm volatile("mma.sync.aligned.m16n8k16.row.col.f32.bf16.bf16.f32 " \
                 "{%0,%1,%2,%3}, {%4,%5,%6,%7}, {%8,%9}, {%0,%1,%2,%3};" \
                 : "+f"((d)[0]), "+f"((d)[1]), "+f"((d)[2]), "+f"((d)[3]) \
                 : "r"((a)[0]), "r"((a)[1]), "r"((a)[2]), "r"((a)[3]), \
                   "r"((b)[0]), "r"((b)[1]))

__device__ __forceinline__ uint32_t f2pack(float v) {
    __nv_bfloat16 h = __float2bfloat16(v);
    __nv_bfloat16 l = __float2bfloat16(v - __bfloat162float(h));
    return (uint32_t)__bfloat16_as_ushort(h) |
           ((uint32_t)__bfloat16_as_ushort(l) << 16);
}

// ---------------------------------------------------------------------------
// Prep: build copy-ready hi/lo weight images + folded GCN bias
// ---------------------------------------------------------------------------
__global__ void prep_kernel(const float* __restrict__ Wg,   // [K][D][C]
                            const float* __restrict__ bg,   // [K][D]
                            const float* __restrict__ Wt,   // [D][D][KT]
                            const float* __restrict__ A)    // [K][V][V]
{
    int idx = blockIdx.x * blockDim.x + threadIdx.x;

    if (idx < 2 * NCH1 * 8192) {
        int e = idx & 8191, img = idx >> 13;
        int ch = img % NCH1, rb = img / NCH1;
        int row = e >> 6, kl = e & 63;
        int kc = ch * CHK + kl;
        int k = kc >> 8, c = kc & 255;
        int d = rb * 128 + row;
        float w = Wg[((size_t)(k * Dd + d)) * Cc + c];
        __nv_bfloat16 h = __float2bfloat16(w);
        __nv_bfloat16 l = __float2bfloat16(w - __bfloat162float(h));
        char* base = d_W1s + (size_t)(rb * NCH1 + ch) * IMGB;
        *(unsigned short*)(base + row * ROWSTRIDE + kl * 2)           = __bfloat16_as_ushort(h);
        *(unsigned short*)(base + PLANE_B + row * ROWSTRIDE + kl * 2) = __bfloat16_as_ushort(l);
    }
    if (idx < 2 * NCH2 * 8192) {
        int e = idx & 8191, img = idx >> 13;
        int ch = img % NCH2, rb = img / NCH2;
        int row = e >> 6, kl = e & 63;
        int kap = ch * CHK + kl;
        int dt = kap >> 8, dp = kap & 255;
        int d = rb * 128 + row;
        float w = Wt[((size_t)(d * Dd + dp)) * KT + dt];
        __nv_bfloat16 h = __float2bfloat16(w);
        __nv_bfloat16 l = __float2bfloat16(w - __bfloat162float(h));
        char* base = d_W2s + (size_t)(rb * NCH2 + ch) * IMGB;
        *(unsigned short*)(base + row * ROWSTRIDE + kl * 2)           = __bfloat16_as_ushort(h);
        *(unsigned short*)(base + PLANE_B + row * ROWSTRIDE + kl * 2) = __bfloat16_as_ushort(l);
    }
    if (idx < Dd * Vv) {
        int d = idx / Vv, w = idx % Vv;
        float acc = 0.f;
        for (int k = 0; k < Kk; k++) {
            float cs = 0.f;
            for (int v = 0; v < Vv; v++) cs += A[k * Vv * Vv + v * Vv + w];
            acc += bg[k * Dd + d] * cs;
        }
        d_bias2[idx] = acc;
    }
}

// ---------------------------------------------------------------------------
// Stage A: xP[kc][col] = packed-bf16( sum_v x[n,c,t,v] * A[k,v,w] )
// ---------------------------------------------------------------------------
__global__ void stageA_kernel(const float* __restrict__ x,
                              const float* __restrict__ A)
{
    __shared__ float As[Kk][Vv][Vv];
    for (int i = threadIdx.x; i < Kk * Vv * Vv; i += blockDim.x)
        ((float*)As)[i] = A[i];
    __syncthreads();

    int idx = blockIdx.x * blockDim.x + threadIdx.x;
    if (idx >= Nn * Cc * Tt) return;
    int t  = idx % Tt;
    int nc = idx / Tt;
    int c  = nc % Cc;
    int n  = nc / Cc;

    const float* xr = x + (size_t)idx * Vv;
    float xv[Vv];
#pragma unroll
    for (int v = 0; v < Vv; v++) xv[v] = xr[v];

    size_t colb = (size_t)n * TV + t * Vv;
#pragma unroll
    for (int k = 0; k < Kk; k++) {
        uint32_t* dst = d_xP + (size_t)(k * Cc + c) * COLS + colb;
#pragma unroll
        for (int w = 0; w < Vv; w++) {
            float acc = 0.f;
#pragma unroll
            for (int v = 0; v < Vv; v++) acc = fmaf(xv[v], As[k][v][w], acc);
            dst[w] = f2pack(acc);
        }
    }
}

// ---------------------------------------------------------------------------
// Split-bf16 warp-MMA GEMM.  Tile 128(M) x 128(N), K-chunk 64, 16 warps (4x4),
// warp tile 32x32.  A loaded via cp.async from pre-swizzled images.
// ---------------------------------------------------------------------------
#define STG_B  (4 * PLANE_B)          // 90112
#define OFF_AH 0
#define OFF_AL PLANE_B
#define OFF_BH (2 * PLANE_B)
#define OFF_BL (3 * PLANE_B)
#define SMEM_DYN (2 * STG_B + 512)    // + tcol table

template <bool GATHER>
__global__ void __launch_bounds__(512, 1)
mma_gemm(const float* __restrict__ btcn)
{
    constexpr int NCH = GATHER ? NCH2 : NCH1;
    const char* Wimg = GATHER ? d_W2s : d_W1s;
    const uint32_t* Bsrc = GATHER ? d_yP : d_xP;

    extern __shared__ char sm[];
    int* tcolS = (int*)(sm + 2 * STG_B);

    const int tid  = threadIdx.x;
    const int wid  = tid >> 5;
    const int lane = tid & 31;
    const int rowBase = blockIdx.x * 128;
    const int colBase = blockIdx.y * 128;

    const int nB  = tid & 127;    // B-fill column (0..127)
    const int grp = tid >> 7;     // 0..3: which 16 k-rows

    if (GATHER && tid < 128) {
        int col = colBase + tid;
        tcolS[tid] = (col % TV) / Vv;
    }
    __syncthreads();

    const uint32_t smBase = smem_u32(sm);

    // ---------------- fill helpers ----------------
    auto cpA = [&](int ch, int buf) {
        const char* src = Wimg + (size_t)(blockIdx.x * NCH + ch) * IMGB;
        uint32_t dst = smBase + buf * STG_B;
#pragma unroll
        for (int r = tid; r < IMGB / 16; r += 512)
            CP_ASYNC16(dst + r * 16, src + r * 16);
        CP_COMMIT();
    };
    auto ldgB = [&](int ch, uint32_t b[16]) {
        int k0row;
        long long srcCol;
        bool valid = true;
        if (!GATHER) {
            k0row = ch * CHK + grp * 16;
            srcCol = colBase + nB;
        } else {
            int dt = ch >> 2;
            k0row = (ch & 3) * 64 + grp * 16;
            int tt = tcolS[nB] + dt - PADT;
            valid = ((unsigned)tt < (unsigned)Tt);
            srcCol = (long long)(colBase + nB) + (long long)(dt - PADT) * Vv;
        }
        const uint32_t* src = Bsrc + (long long)k0row * COLS + srcCol;
#pragma unroll
        for (int j = 0; j < 8; j++) {
            b[2 * j]     = valid ? src[(2 * j) * COLS]     : 0u;
            b[2 * j + 1] = valid ? src[(2 * j + 1) * COLS] : 0u;
        }
    };
    auto stsB = [&](int buf, const uint32_t b[16]) {
        char* bh = sm + buf * STG_B + OFF_BH + nB * ROWSTRIDE + grp * 32;
        char* bl = sm + buf * STG_B + OFF_BL + nB * ROWSTRIDE + grp * 32;
#pragma unroll
        for (int j = 0; j < 8; j++) {
            uint32_t w0 = b[2 * j], w1 = b[2 * j + 1];
            *(uint32_t*)(bh + j * 4) = __byte_perm(w0, w1, 0x5410);  // hi pair
            *(uint32_t*)(bl + j * 4) = __byte_perm(w0, w1, 0x7632);  // lo pair
        }
    };

    // ---------------- accumulators ----------------
    float acc[2][4][4];
#pragma unroll
    for (int i = 0; i < 2; i++)
#pragma unroll
        for (int j = 0; j < 4; j++)
#pragma unroll
            for (int r = 0; r < 4; r++) acc[i][j][r] = 0.f;

    const int wm = wid >> 2;       // 0..3 -> 32-row strip
    const int wn = wid & 3;        // 0..3 -> 32-col strip

    const int aRow = wm * 32 + ((lane >> 3) & 1) * 8 + (lane & 7);
    const int aCol = (lane >> 4) * 8;
    const int bRow = wn * 32 + ((lane >> 4) & 1) * 8 + (lane & 7);
    const int bCol = ((lane >> 3) & 1) * 8;

    // ---------------- prologue: fill buffer 0 ----------------
    {
        uint32_t b[16];
        cpA(0, 0);
        ldgB(0, b);
        CP_WAIT0();
        stsB(0, b);
    }
    __syncthreads();

    uint32_t bReg[16];

    for (int i = 0; i < NCH; i++) {
        const uint32_t curS = smBase + (i & 1) * STG_B;

        if (i + 1 < NCH) {
            cpA(i + 1, (i + 1) & 1);    // async into the free buffer
            ldgB(i + 1, bReg);
        }

        // ---------------- compute chunk i ----------------
#pragma unroll
        for (int ks = 0; ks < 4; ks++) {
            uint32_t ah[2][4], al[2][4], bh[4][2], bl[4][2];
#pragma unroll
            for (int mf = 0; mf < 2; mf++) {
                uint32_t ad = curS + OFF_AH +
                              (aRow + mf * 16) * ROWSTRIDE + (aCol + ks * 16) * 2;
                LDSM4(ah[mf][0], ah[mf][1], ah[mf][2], ah[mf][3], ad);
                LDSM4(al[mf][0], al[mf][1], al[mf][2], al[mf][3], ad + PLANE_B);
            }
#pragma unroll
            for (int g = 0; g < 2; g++) {
                uint32_t bd = curS + OFF_BH +
                              (bRow + g * 16) * ROWSTRIDE + (bCol + ks * 16) * 2;
                uint32_t r0, r1, r2, r3;
                LDSM4(r0, r1, r2, r3, bd);
                bh[g * 2][0] = r0; bh[g * 2][1] = r1;
                bh[g * 2 + 1][0] = r2; bh[g * 2 + 1][1] = r3;
                LDSM4(r0, r1, r2, r3, bd + PLANE_B);
                bl[g * 2][0] = r0; bl[g * 2][1] = r1;
                bl[g * 2 + 1][0] = r2; bl[g * 2 + 1][1] = r3;
            }
#pragma unroll
            for (int mf = 0; mf < 2; mf++)
#pragma unroll
                for (int nf = 0; nf < 4; nf++) {
                    MMA16816(acc[mf][nf], ah[mf], bh[nf]);
                    MMA16816(acc[mf][nf], al[mf], bh[nf]);
                    MMA16816(acc[mf][nf], ah[mf], bl[nf]);
                }
        }

        if (i + 1 < NCH) {
            CP_WAIT0();                 // A(i+1) landed
            stsB((i + 1) & 1, bReg);
        }
        __syncthreads();
    }

    // ---------------- epilogue ----------------
    const int mB = rowBase + wm * 32 + (lane >> 2);
    const int nB0 = colBase + wn * 32 + (lane & 3) * 2;
#pragma unroll
    for (int mf = 0; mf < 2; mf++) {
#pragma unroll
        for (int h = 0; h < 2; h++) {          // row halves (+0 / +8)
            int m = mB + mf * 16 + h * 8;
#pragma unroll
            for (int nf = 0; nf < 4; nf++) {
                int col = nB0 + nf * 8;
                float v0 = acc[mf][nf][2 * h];
                float v1 = acc[mf][nf][2 * h + 1];
                if (!GATHER) {
                    v0 += d_bias2[m * Vv + (col % Vv)];
                    v1 += d_bias2[m * Vv + ((col + 1) % Vv)];
                    uint2 pk = make_uint2(f2pack(v0), f2pack(v1));
                    *(uint2*)(d_yP + (size_t)m * COLS + col) = pk;
                } else {
                    float bi = btcn[m];
                    float2 f = make_float2(v0 + bi, v1 + bi);
                    *(float2*)(d_z + (size_t)m * COLS + col) = f;
                }
            }
        }
    }
}

// ---------------------------------------------------------------------------
// BN statistics (deterministic, one block per channel)
// ---------------------------------------------------------------------------
__global__ void bnstats_kernel(const float* __restrict__ gamma,
                               const float* __restrict__ beta)
{
    int d = blockIdx.x;
    const float* zr = d_z + (size_t)d * COLS;
    float s = 0.f, sq = 0.f;
    for (int i = threadIdx.x; i < COLS; i += 256) {
        float v = zr[i];
        s  += v;
        sq += v * v;
    }
    __shared__ float sh1[256], sh2[256];
    sh1[threadIdx.x] = s;
    sh2[threadIdx.x] = sq;
    __syncthreads();
    for (int o = 128; o > 0; o >>= 1) {
        if (threadIdx.x < o) {
            sh1[threadIdx.x] += sh1[threadIdx.x + o];
            sh2[threadIdx.x] += sh2[threadIdx.x + o];
        }
        __syncthreads();
    }
    if (threadIdx.x == 0) {
        float mean = sh1[0] * (1.0f / COLS);
        float var  = sh2[0] * (1.0f / COLS) - mean * mean;
        float r    = rsqrtf(var + 1e-5f);
        d_scale[d] = gamma[d] * r;
        d_shift[d] = beta[d] - gamma[d] * mean * r;
    }
}

// ---------------------------------------------------------------------------
// Finalize: BN apply + residual + ReLU, transpose [d][n,t,v] -> [n][d][t][v]
// ---------------------------------------------------------------------------
__global__ void finalize_kernel(const float* __restrict__ x,
                                float* __restrict__ out)
{
    int e = blockIdx.x * 256 + threadIdx.x;
    int n = e / (Dd * TV);
    int r = e % (Dd * TV);
    int d = r / TV;
    int s = r % TV;
    float z = d_z[(size_t)d * COLS + n * TV + s];
    float v = fmaf(d_scale[d], z, d_shift[d]) + x[e];
    out[e] = fmaxf(v, 0.f);
}

// ---------------------------------------------------------------------------
extern "C" void kernel_launch(void* const* d_in, const int* in_sizes, int n_in,
                              void* d_out, int out_size)
{
    const float* x     = (const float*)d_in[0];
    const float* A     = (const float*)d_in[1];
    const float* W_gcn = (const float*)d_in[2];
    const float* b_gcn = (const float*)d_in[3];
    const float* W_tcn = (const float*)d_in[4];
    const float* b_tcn = (const float*)d_in[5];
    const float* gamma = (const float*)d_in[6];
    const float* beta  = (const float*)d_in[7];
    float* out = (float*)d_out;

    cudaFuncSetAttribute(mma_gemm<false>, cudaFuncAttributeMaxDynamicSharedMemorySize, SMEM_DYN);
    cudaFuncSetAttribute(mma_gemm<true>,  cudaFuncAttributeMaxDynamicSharedMemorySize, SMEM_DYN);

    prep_kernel<<<(2 * NCH2 * 8192 + 255) / 256, 256>>>(W_gcn, b_gcn, W_tcn, A);
    stageA_kernel<<<(Nn * Cc * Tt + 255) / 256, 256>>>(x, A);

    mma_gemm<false><<<dim3(2, 400), 512, SMEM_DYN>>>(nullptr);
    mma_gemm<true><<<dim3(2, 400), 512, SMEM_DYN>>>(b_tcn);

    bnstats_kernel<<<Dd, 256>>>(gamma, beta);
    finalize_kernel<<<(Nn * Dd * TV) / 256, 256>>>(x, out);
}

// round 13
// speedup vs baseline: 3.4388x; 1.2749x over previous
#include <cuda_runtime.h>
#include <cuda_fp16.h>
#include <cstdint>

// Problem constants
#define Nn   32
#define Cc   256
#define Tt   64
#define Vv   25
#define Kk   3
#define Dd   256
#define KT   9
#define PADT 4
#define TV   1600     // Tt*Vv
#define COLS 51200    // Nn*Tt*Vv
#define KC   768      // GCN contraction dim
#define KD   2304     // TCN contraction dim
#define CHK  64       // K per chunk
#define NCH1 12       // KC/64
#define NCH2 36       // KD/64

// smem plane: 128 rows x 176B (64 fp16 = 128B + 48B pad; 44 words/row keeps
// both ldmatrix reads and sts writes conflict-free)
#define ROWSTRIDE 176
#define PLANE_B   (128 * ROWSTRIDE)   // 22528
// weight image = ONE fp16 plane per chunk (weights rounded, not split)
#define IMGW      PLANE_B

// ---------------------------------------------------------------------------
// Scratch (module-load allocated)
__device__ uint32_t d_xP[(size_t)KC * COLS];   // packed fp16 hi|lo<<16
__device__ uint32_t d_yP[(size_t)Dd * COLS];   // packed fp16 hi|lo<<16
__device__ float    d_z [(size_t)Dd * COLS];
__device__ char d_W1s[2 * NCH1 * IMGW];
__device__ char d_W2s[2 * NCH2 * IMGW];
__device__ float d_bias2[Dd * Vv];
__device__ float d_scale[Dd];
__device__ float d_shift[Dd];

// ---------------------------------------------------------------------------
__device__ __forceinline__ uint32_t smem_u32(const void* p) {
    uint32_t a;
    asm("{ .reg .u64 t; cvta.to.shared.u64 t, %1; cvt.u32.u64 %0, t; }"
        : "=r"(a) : "l"(p));
    return a;
}

#define CP_ASYNC16(smaddr, gptr) \
    asm volatile("cp.async.cg.shared.global [%0], [%1], 16;" \
                 :: "r"(smaddr), "l"(gptr))
#define CP_COMMIT() asm volatile("cp.async.commit_group;")
#define CP_WAIT0()  asm volatile("cp.async.wait_group 0;" ::: "memory")

#define LDSM4(r0, r1, r2, r3, addr) \
    asm volatile("ldmatrix.sync.aligned.m8n8.x4.shared.b16 {%0,%1,%2,%3}, [%4];" \
                 : "=r"(r0), "=r"(r1), "=r"(r2), "=r"(r3) : "r"(addr))

#define MMAH(d, a, b) \
    asm volatile("mma.sync.aligned.m16n8k16.row.col.f32.f16.f16.f32 " \
                 "{%0,%1,%2,%3}, {%4,%5,%6,%7}, {%8,%9}, {%0,%1,%2,%3};" \
                 : "+f"((d)[0]), "+f"((d)[1]), "+f"((d)[2]), "+f"((d)[3]) \
                 : "r"((a)[0]), "r"((a)[1]), "r"((a)[2]), "r"((a)[3]), \
                   "r"((b)[0]), "r"((b)[1]))

// pack value as fp16 hi + fp16 lo (hi|lo<<16); hi+lo ~ v to ~2^-22
__device__ __forceinline__ uint32_t f2packh(float v) {
    __half h = __float2half_rn(v);
    __half l = __float2half_rn(v - __half2float(h));
    return (uint32_t)__half_as_ushort(h) |
           ((uint32_t)__half_as_ushort(l) << 16);
}

// ---------------------------------------------------------------------------
// Prep: fp16-rounded weight images (single plane) + folded GCN bias
// ---------------------------------------------------------------------------
__global__ void prep_kernel(const float* __restrict__ Wg,   // [K][D][C]
                            const float* __restrict__ bg,   // [K][D]
                            const float* __restrict__ Wt,   // [D][D][KT]
                            const float* __restrict__ A)    // [K][V][V]
{
    int idx = blockIdx.x * blockDim.x + threadIdx.x;

    if (idx < 2 * NCH1 * 8192) {
        int e = idx & 8191, img = idx >> 13;
        int ch = img % NCH1, rb = img / NCH1;
        int row = e >> 6, kl = e & 63;
        int kc = ch * CHK + kl;
        int k = kc >> 8, c = kc & 255;
        int d = rb * 128 + row;
        float w = Wg[((size_t)(k * Dd + d)) * Cc + c];
        char* base = d_W1s + (size_t)(rb * NCH1 + ch) * IMGW;
        *(unsigned short*)(base + row * ROWSTRIDE + kl * 2) =
            __half_as_ushort(__float2half_rn(w));
    }
    if (idx < 2 * NCH2 * 8192) {
        int e = idx & 8191, img = idx >> 13;
        int ch = img % NCH2, rb = img / NCH2;
        int row = e >> 6, kl = e & 63;
        int kap = ch * CHK + kl;
        int dt = kap >> 8, dp = kap & 255;
        int d = rb * 128 + row;
        float w = Wt[((size_t)(d * Dd + dp)) * KT + dt];
        char* base = d_W2s + (size_t)(rb * NCH2 + ch) * IMGW;
        *(unsigned short*)(base + row * ROWSTRIDE + kl * 2) =
            __half_as_ushort(__float2half_rn(w));
    }
    if (idx < Dd * Vv) {
        int d = idx / Vv, w = idx % Vv;
        float acc = 0.f;
        for (int k = 0; k < Kk; k++) {
            float cs = 0.f;
            for (int v = 0; v < Vv; v++) cs += A[k * Vv * Vv + v * Vv + w];
            acc += bg[k * Dd + d] * cs;
        }
        d_bias2[idx] = acc;
    }
}

// ---------------------------------------------------------------------------
// Stage A: xP[kc][col] = packed-fp16( sum_v x[n,c,t,v] * A[k,v,w] )
// ---------------------------------------------------------------------------
__global__ void stageA_kernel(const float* __restrict__ x,
                              const float* __restrict__ A)
{
    __shared__ float As[Kk][Vv][Vv];
    for (int i = threadIdx.x; i < Kk * Vv * Vv; i += blockDim.x)
        ((float*)As)[i] = A[i];
    __syncthreads();

    int idx = blockIdx.x * blockDim.x + threadIdx.x;
    if (idx >= Nn * Cc * Tt) return;
    int t  = idx % Tt;
    int nc = idx / Tt;
    int c  = nc % Cc;
    int n  = nc / Cc;

    const float* xr = x + (size_t)idx * Vv;
    float xv[Vv];
#pragma unroll
    for (int v = 0; v < Vv; v++) xv[v] = xr[v];

    size_t colb = (size_t)n * TV + t * Vv;
#pragma unroll
    for (int k = 0; k < Kk; k++) {
        uint32_t* dst = d_xP + (size_t)(k * Cc + c) * COLS + colb;
#pragma unroll
        for (int w = 0; w < Vv; w++) {
            float acc = 0.f;
#pragma unroll
            for (int v = 0; v < Vv; v++) acc = fmaf(xv[v], As[k][v][w], acc);
            dst[w] = f2packh(acc);
        }
    }
}

// ---------------------------------------------------------------------------
// fp16 asymmetric-split warp-MMA GEMM.  Tile 128x128, K-chunk 64, 16 warps,
// warp tile 32x32.  Weights fp16-rounded (1 plane); data split hi/lo (2 planes).
// acc += Aw*(Bh + Bl)  -> 2 MMAs per fragment pair.
// ---------------------------------------------------------------------------
#define STG_B  (3 * PLANE_B)          // 67584
#define OFF_AW 0
#define OFF_BH PLANE_B
#define OFF_BL (2 * PLANE_B)
#define SMEM_DYN (2 * STG_B + 512)    // + tcol table

template <bool GATHER>
__global__ void __launch_bounds__(512, 1)
mma_gemm(const float* __restrict__ btcn)
{
    constexpr int NCH = GATHER ? NCH2 : NCH1;
    const char* Wimg = GATHER ? d_W2s : d_W1s;
    const uint32_t* Bsrc = GATHER ? d_yP : d_xP;

    extern __shared__ char sm[];
    int* tcolS = (int*)(sm + 2 * STG_B);

    const int tid  = threadIdx.x;
    const int wid  = tid >> 5;
    const int lane = tid & 31;
    const int rowBase = blockIdx.x * 128;
    const int colBase = blockIdx.y * 128;

    const int nB  = tid & 127;    // B-fill column (0..127)
    const int grp = tid >> 7;     // 0..3: which 16 k-rows

    if (GATHER && tid < 128) {
        int col = colBase + tid;
        tcolS[tid] = (col % TV) / Vv;
    }
    __syncthreads();

    const uint32_t smBase = smem_u32(sm);

    // ---------------- fill helpers ----------------
    auto cpA = [&](int ch, int buf) {
        const char* src = Wimg + (size_t)(blockIdx.x * NCH + ch) * IMGW;
        uint32_t dst = smBase + buf * STG_B;
#pragma unroll
        for (int r = tid; r < IMGW / 16; r += 512)
            CP_ASYNC16(dst + r * 16, src + r * 16);
        CP_COMMIT();
    };
    auto ldgB = [&](int ch, uint32_t b[16]) {
        int k0row;
        long long srcCol;
        bool valid = true;
        if (!GATHER) {
            k0row = ch * CHK + grp * 16;
            srcCol = colBase + nB;
        } else {
            int dt = ch >> 2;
            k0row = (ch & 3) * 64 + grp * 16;
            int tt = tcolS[nB] + dt - PADT;
            valid = ((unsigned)tt < (unsigned)Tt);
            srcCol = (long long)(colBase + nB) + (long long)(dt - PADT) * Vv;
        }
        const uint32_t* src = Bsrc + (long long)k0row * COLS + srcCol;
#pragma unroll
        for (int j = 0; j < 8; j++) {
            b[2 * j]     = valid ? src[(2 * j) * COLS]     : 0u;
            b[2 * j + 1] = valid ? src[(2 * j + 1) * COLS] : 0u;
        }
    };
    auto stsB = [&](int buf, const uint32_t b[16]) {
        char* bh = sm + buf * STG_B + OFF_BH + nB * ROWSTRIDE + grp * 32;
        char* bl = sm + buf * STG_B + OFF_BL + nB * ROWSTRIDE + grp * 32;
#pragma unroll
        for (int j = 0; j < 8; j++) {
            uint32_t w0 = b[2 * j], w1 = b[2 * j + 1];
            *(uint32_t*)(bh + j * 4) = __byte_perm(w0, w1, 0x5410);  // hi pair
            *(uint32_t*)(bl + j * 4) = __byte_perm(w0, w1, 0x7632);  // lo pair
        }
    };

    // ---------------- accumulators ----------------
    float acc[2][4][4];
#pragma unroll
    for (int i = 0; i < 2; i++)
#pragma unroll
        for (int j = 0; j < 4; j++)
#pragma unroll
            for (int r = 0; r < 4; r++) acc[i][j][r] = 0.f;

    const int wm = wid >> 2;       // 0..3 -> 32-row strip
    const int wn = wid & 3;        // 0..3 -> 32-col strip

    const int aRow = wm * 32 + ((lane >> 3) & 1) * 8 + (lane & 7);
    const int aCol = (lane >> 4) * 8;
    const int bRow = wn * 32 + ((lane >> 4) & 1) * 8 + (lane & 7);
    const int bCol = ((lane >> 3) & 1) * 8;

    // ---------------- prologue: fill buffer 0 ----------------
    {
        uint32_t b[16];
        cpA(0, 0);
        ldgB(0, b);
        CP_WAIT0();
        stsB(0, b);
    }
    __syncthreads();

    uint32_t bReg[16];

    for (int i = 0; i < NCH; i++) {
        const uint32_t curS = smBase + (i & 1) * STG_B;

        if (i + 1 < NCH) {
            cpA(i + 1, (i + 1) & 1);    // async into the free buffer
            ldgB(i + 1, bReg);
        }

        // ---------------- compute chunk i ----------------
#pragma unroll
        for (int ks = 0; ks < 4; ks++) {
            uint32_t aw[2][4], bh[4][2], bl[4][2];
#pragma unroll
            for (int mf = 0; mf < 2; mf++) {
                uint32_t ad = curS + OFF_AW +
                              (aRow + mf * 16) * ROWSTRIDE + (aCol + ks * 16) * 2;
                LDSM4(aw[mf][0], aw[mf][1], aw[mf][2], aw[mf][3], ad);
            }
#pragma unroll
            for (int g = 0; g < 2; g++) {
                uint32_t bd = curS + OFF_BH +
                              (bRow + g * 16) * ROWSTRIDE + (bCol + ks * 16) * 2;
                uint32_t r0, r1, r2, r3;
                LDSM4(r0, r1, r2, r3, bd);
                bh[g * 2][0] = r0; bh[g * 2][1] = r1;
                bh[g * 2 + 1][0] = r2; bh[g * 2 + 1][1] = r3;
                LDSM4(r0, r1, r2, r3, bd + PLANE_B);
                bl[g * 2][0] = r0; bl[g * 2][1] = r1;
                bl[g * 2 + 1][0] = r2; bl[g * 2 + 1][1] = r3;
            }
#pragma unroll
            for (int mf = 0; mf < 2; mf++)
#pragma unroll
                for (int nf = 0; nf < 4; nf++) {
                    MMAH(acc[mf][nf], aw[mf], bh[nf]);
                    MMAH(acc[mf][nf], aw[mf], bl[nf]);
                }
        }

        if (i + 1 < NCH) {
            CP_WAIT0();                 // A(i+1) landed
            stsB((i + 1) & 1, bReg);
        }
        __syncthreads();
    }

    // ---------------- epilogue ----------------
    const int mB = rowBase + wm * 32 + (lane >> 2);
    const int nB0 = colBase + wn * 32 + (lane & 3) * 2;
#pragma unroll
    for (int mf = 0; mf < 2; mf++) {
#pragma unroll
        for (int h = 0; h < 2; h++) {          // row halves (+0 / +8)
            int m = mB + mf * 16 + h * 8;
#pragma unroll
            for (int nf = 0; nf < 4; nf++) {
                int col = nB0 + nf * 8;
                float v0 = acc[mf][nf][2 * h];
                float v1 = acc[mf][nf][2 * h + 1];
                if (!GATHER) {
                    v0 += d_bias2[m * Vv + (col % Vv)];
                    v1 += d_bias2[m * Vv + ((col + 1) % Vv)];
                    uint2 pk = make_uint2(f2packh(v0), f2packh(v1));
                    *(uint2*)(d_yP + (size_t)m * COLS + col) = pk;
                } else {
                    float bi = btcn[m];
                    float2 f = make_float2(v0 + bi, v1 + bi);
                    *(float2*)(d_z + (size_t)m * COLS + col) = f;
                }
            }
        }
    }
}

// ---------------------------------------------------------------------------
// BN statistics (deterministic, one block per channel)
// ---------------------------------------------------------------------------
__global__ void bnstats_kernel(const float* __restrict__ gamma,
                               const float* __restrict__ beta)
{
    int d = blockIdx.x;
    const float* zr = d_z + (size_t)d * COLS;
    float s = 0.f, sq = 0.f;
    for (int i = threadIdx.x; i < COLS; i += 256) {
        float v = zr[i];
        s  += v;
        sq += v * v;
    }
    __shared__ float sh1[256], sh2[256];
    sh1[threadIdx.x] = s;
    sh2[threadIdx.x] = sq;
    __syncthreads();
    for (int o = 128; o > 0; o >>= 1) {
        if (threadIdx.x < o) {
            sh1[threadIdx.x] += sh1[threadIdx.x + o];
            sh2[threadIdx.x] += sh2[threadIdx.x + o];
        }
        __syncthreads();
    }
    if (threadIdx.x == 0) {
        float mean = sh1[0] * (1.0f / COLS);
        float var  = sh2[0] * (1.0f / COLS) - mean * mean;
        float r    = rsqrtf(var + 1e-5f);
        d_scale[d] = gamma[d] * r;
        d_shift[d] = beta[d] - gamma[d] * mean * r;
    }
}

// ---------------------------------------------------------------------------
// Finalize: BN apply + residual + ReLU, transpose [d][n,t,v] -> [n][d][t][v]
// ---------------------------------------------------------------------------
__global__ void finalize_kernel(const float* __restrict__ x,
                                float* __restrict__ out)
{
    int e = blockIdx.x * 256 + threadIdx.x;
    int n = e / (Dd * TV);
    int r = e % (Dd * TV);
    int d = r / TV;
    int s = r % TV;
    float z = d_z[(size_t)d * COLS + n * TV + s];
    float v = fmaf(d_scale[d], z, d_shift[d]) + x[e];
    out[e] = fmaxf(v, 0.f);
}

// ---------------------------------------------------------------------------
extern "C" void kernel_launch(void* const* d_in, const int* in_sizes, int n_in,
                              void* d_out, int out_size)
{
    const float* x     = (const float*)d_in[0];
    const float* A     = (const float*)d_in[1];
    const float* W_gcn = (const float*)d_in[2];
    const float* b_gcn = (const float*)d_in[3];
    const float* W_tcn = (const float*)d_in[4];
    const float* b_tcn = (const float*)d_in[5];
    const float* gamma = (const float*)d_in[6];
    const float* beta  = (const float*)d_in[7];
    float* out = (float*)d_out;

    cudaFuncSetAttribute(mma_gemm<false>, cudaFuncAttributeMaxDynamicSharedMemorySize, SMEM_DYN);
    cudaFuncSetAttribute(mma_gemm<true>,  cudaFuncAttributeMaxDynamicSharedMemorySize, SMEM_DYN);

    prep_kernel<<<(2 * NCH2 * 8192 + 255) / 256, 256>>>(W_gcn, b_gcn, W_tcn, A);
    stageA_kernel<<<(Nn * Cc * Tt + 255) / 256, 256>>>(x, A);

    mma_gemm<false><<<dim3(2, 400), 512, SMEM_DYN>>>(nullptr);
    mma_gemm<true><<<dim3(2, 400), 512, SMEM_DYN>>>(b_tcn);

    bnstats_kernel<<<Dd, 256>>>(gamma, beta);
    finalize_kernel<<<(Nn * Dd * TV) / 256, 256>>>(x, out);
}

// round 16
// speedup vs baseline: 3.9234x; 1.1409x over previous
#include <cuda_runtime.h>
#include <cuda_fp16.h>
#include <cstdint>

// Problem constants
#define Nn   32
#define Cc   256
#define Tt   64
#define Vv   25
#define Kk   3
#define Dd   256
#define KT   9
#define PADT 4
#define TV   1600     // Tt*Vv
#define COLS 51200    // Nn*Tt*Vv
#define KC   768      // GCN contraction dim
#define KD   2304     // TCN contraction dim
#define CHK  64       // K per chunk
#define NCH1 12       // KC/64
#define NCH2 36       // KD/64

// smem plane: 128 rows x 176B (64 fp16 = 128B + 48B pad; 44 words/row keeps
// both ldmatrix reads and sts writes conflict-free)
#define ROWSTRIDE 176
#define PLANE_B   (128 * ROWSTRIDE)   // 22528
#define IMGW      PLANE_B             // weight image: one fp16 plane per chunk

// ---------------------------------------------------------------------------
// Scratch (module-load allocated)
__device__ __half d_xP[(size_t)KC * COLS];   // fp16 (rounded)
__device__ __half d_yP[(size_t)Dd * COLS];   // fp16 (rounded)
__device__ float  d_z [(size_t)Dd * COLS];
__device__ char d_W1s[2 * NCH1 * IMGW];
__device__ char d_W2s[2 * NCH2 * IMGW];
__device__ float d_bias2[Dd * Vv];
__device__ float d_scale[Dd];
__device__ float d_shift[Dd];

// ---------------------------------------------------------------------------
__device__ __forceinline__ uint32_t smem_u32(const void* p) {
    uint32_t a;
    asm("{ .reg .u64 t; cvta.to.shared.u64 t, %1; cvt.u32.u64 %0, t; }"
        : "=r"(a) : "l"(p));
    return a;
}

#define CP_ASYNC16(smaddr, gptr) \
    asm volatile("cp.async.cg.shared.global [%0], [%1], 16;" \
                 :: "r"(smaddr), "l"(gptr))
#define CP_COMMIT() asm volatile("cp.async.commit_group;")
#define CP_WAIT0()  asm volatile("cp.async.wait_group 0;" ::: "memory")

#define LDSM4(r0, r1, r2, r3, addr) \
    asm volatile("ldmatrix.sync.aligned.m8n8.x4.shared.b16 {%0,%1,%2,%3}, [%4];" \
                 : "=r"(r0), "=r"(r1), "=r"(r2), "=r"(r3) : "r"(addr))

#define MMAH(d, a, b) \
    asm volatile("mma.sync.aligned.m16n8k16.row.col.f32.f16.f16.f32 " \
                 "{%0,%1,%2,%3}, {%4,%5,%6,%7}, {%8,%9}, {%0,%1,%2,%3};" \
                 : "+f"((d)[0]), "+f"((d)[1]), "+f"((d)[2]), "+f"((d)[3]) \
                 : "r"((a)[0]), "r"((a)[1]), "r"((a)[2]), "r"((a)[3]), \
                   "r"((b)[0]), "r"((b)[1]))

// ---------------------------------------------------------------------------
// Prep: fp16-rounded weight images (single plane) + folded GCN bias
// ---------------------------------------------------------------------------
__global__ void prep_kernel(const float* __restrict__ Wg,   // [K][D][C]
                            const float* __restrict__ bg,   // [K][D]
                            const float* __restrict__ Wt,   // [D][D][KT]
                            const float* __restrict__ A)    // [K][V][V]
{
    int idx = blockIdx.x * blockDim.x + threadIdx.x;

    if (idx < 2 * NCH1 * 8192) {
        int e = idx & 8191, img = idx >> 13;
        int ch = img % NCH1, rb = img / NCH1;
        int row = e >> 6, kl = e & 63;
        int kc = ch * CHK + kl;
        int k = kc >> 8, c = kc & 255;
        int d = rb * 128 + row;
        float w = Wg[((size_t)(k * Dd + d)) * Cc + c];
        char* base = d_W1s + (size_t)(rb * NCH1 + ch) * IMGW;
        *(unsigned short*)(base + row * ROWSTRIDE + kl * 2) =
            __half_as_ushort(__float2half_rn(w));
    }
    if (idx < 2 * NCH2 * 8192) {
        int e = idx & 8191, img = idx >> 13;
        int ch = img % NCH2, rb = img / NCH2;
        int row = e >> 6, kl = e & 63;
        int kap = ch * CHK + kl;
        int dt = kap >> 8, dp = kap & 255;
        int d = rb * 128 + row;
        float w = Wt[((size_t)(d * Dd + dp)) * KT + dt];
        char* base = d_W2s + (size_t)(rb * NCH2 + ch) * IMGW;
        *(unsigned short*)(base + row * ROWSTRIDE + kl * 2) =
            __half_as_ushort(__float2half_rn(w));
    }
    if (idx < Dd * Vv) {
        int d = idx / Vv, w = idx % Vv;
        float acc = 0.f;
        for (int k = 0; k < Kk; k++) {
            float cs = 0.f;
            for (int v = 0; v < Vv; v++) cs += A[k * Vv * Vv + v * Vv + w];
            acc += bg[k * Dd + d] * cs;
        }
        d_bias2[idx] = acc;
    }
}

// ---------------------------------------------------------------------------
// Stage A: xP[kc][col] = fp16( sum_v x[n,c,t,v] * A[k,v,w] )
// ---------------------------------------------------------------------------
__global__ void stageA_kernel(const float* __restrict__ x,
                              const float* __restrict__ A)
{
    __shared__ float As[Kk][Vv][Vv];
    for (int i = threadIdx.x; i < Kk * Vv * Vv; i += blockDim.x)
        ((float*)As)[i] = A[i];
    __syncthreads();

    int idx = blockIdx.x * blockDim.x + threadIdx.x;
    if (idx >= Nn * Cc * Tt) return;
    int t  = idx % Tt;
    int nc = idx / Tt;
    int c  = nc % Cc;
    int n  = nc / Cc;

    const float* xr = x + (size_t)idx * Vv;
    float xv[Vv];
#pragma unroll
    for (int v = 0; v < Vv; v++) xv[v] = xr[v];

    size_t colb = (size_t)n * TV + t * Vv;
#pragma unroll
    for (int k = 0; k < Kk; k++) {
        __half* dst = d_xP + (size_t)(k * Cc + c) * COLS + colb;
#pragma unroll
        for (int w = 0; w < Vv; w++) {
            float acc = 0.f;
#pragma unroll
            for (int v = 0; v < Vv; v++) acc = fmaf(xv[v], As[k][v][w], acc);
            dst[w] = __float2half_rn(acc);
        }
    }
}

// ---------------------------------------------------------------------------
// fp16 warp-MMA GEMM.  Tile 128x128, K-chunk 64, 16 warps (4x4), warp 32x32.
// Weights fp16 (1 plane, cp.async); data fp16 (1 plane, gathered).
// 1 MMA per fragment pair.
// ---------------------------------------------------------------------------
#define STG_B  (2 * PLANE_B)          // 45056
#define OFF_AW 0
#define OFF_B  PLANE_B
#define SMEM_DYN (2 * STG_B + 512)    // + tcol table

template <bool GATHER>
__global__ void __launch_bounds__(512, 1)
mma_gemm(const float* __restrict__ btcn)
{
    constexpr int NCH = GATHER ? NCH2 : NCH1;
    const char* Wimg = GATHER ? d_W2s : d_W1s;
    const __half* Bsrc = GATHER ? d_yP : d_xP;

    extern __shared__ char sm[];
    int* tcolS = (int*)(sm + 2 * STG_B);

    const int tid  = threadIdx.x;
    const int wid  = tid >> 5;
    const int lane = tid & 31;
    const int rowBase = blockIdx.x * 128;
    const int colBase = blockIdx.y * 128;

    const int nB  = tid & 127;    // B-fill column (0..127)
    const int grp = tid >> 7;     // 0..3: which 16 k-rows

    if (GATHER && tid < 128) {
        int col = colBase + tid;
        tcolS[tid] = (col % TV) / Vv;
    }
    __syncthreads();

    const uint32_t smBase = smem_u32(sm);

    // ---------------- fill helpers ----------------
    auto cpA = [&](int ch, int buf) {
        const char* src = Wimg + (size_t)(blockIdx.x * NCH + ch) * IMGW;
        uint32_t dst = smBase + buf * STG_B;
#pragma unroll
        for (int r = tid; r < IMGW / 16; r += 512)
            CP_ASYNC16(dst + r * 16, src + r * 16);
        CP_COMMIT();
    };
    auto ldgB = [&](int ch, unsigned short b[16]) {
        int k0row;
        long long srcCol;
        bool valid = true;
        if (!GATHER) {
            k0row = ch * CHK + grp * 16;
            srcCol = colBase + nB;
        } else {
            int dt = ch >> 2;
            k0row = (ch & 3) * 64 + grp * 16;
            int tt = tcolS[nB] + dt - PADT;
            valid = ((unsigned)tt < (unsigned)Tt);
            srcCol = (long long)(colBase + nB) + (long long)(dt - PADT) * Vv;
        }
        const unsigned short* src =
            (const unsigned short*)Bsrc + (long long)k0row * COLS + srcCol;
#pragma unroll
        for (int j = 0; j < 16; j++)
            b[j] = valid ? src[j * COLS] : (unsigned short)0;
    };
    auto stsB = [&](int buf, const unsigned short b[16]) {
        char* bp = sm + buf * STG_B + OFF_B + nB * ROWSTRIDE + grp * 32;
#pragma unroll
        for (int j = 0; j < 8; j++)
            *(uint32_t*)(bp + j * 4) =
                (uint32_t)b[2 * j] | ((uint32_t)b[2 * j + 1] << 16);
    };

    // ---------------- accumulators ----------------
    float acc[2][4][4];
#pragma unroll
    for (int i = 0; i < 2; i++)
#pragma unroll
        for (int j = 0; j < 4; j++)
#pragma unroll
            for (int r = 0; r < 4; r++) acc[i][j][r] = 0.f;

    const int wm = wid >> 2;       // 0..3 -> 32-row strip
    const int wn = wid & 3;        // 0..3 -> 32-col strip

    const int aRow = wm * 32 + ((lane >> 3) & 1) * 8 + (lane & 7);
    const int aCol = (lane >> 4) * 8;
    const int bRow = wn * 32 + ((lane >> 4) & 1) * 8 + (lane & 7);
    const int bCol = ((lane >> 3) & 1) * 8;

    // ---------------- prologue: fill buffer 0 ----------------
    {
        unsigned short b[16];
        cpA(0, 0);
        ldgB(0, b);
        CP_WAIT0();
        stsB(0, b);
    }
    __syncthreads();

    unsigned short bReg[16];

    for (int i = 0; i < NCH; i++) {
        const uint32_t curS = smBase + (i & 1) * STG_B;

        if (i + 1 < NCH) {
            cpA(i + 1, (i + 1) & 1);    // async into the free buffer
            ldgB(i + 1, bReg);
        }

        // ---------------- compute chunk i ----------------
#pragma unroll
        for (int ks = 0; ks < 4; ks++) {
            uint32_t aw[2][4], bh[4][2];
#pragma unroll
            for (int mf = 0; mf < 2; mf++) {
                uint32_t ad = curS + OFF_AW +
                              (aRow + mf * 16) * ROWSTRIDE + (aCol + ks * 16) * 2;
                LDSM4(aw[mf][0], aw[mf][1], aw[mf][2], aw[mf][3], ad);
            }
#pragma unroll
            for (int g = 0; g < 2; g++) {
                uint32_t bd = curS + OFF_B +
                              (bRow + g * 16) * ROWSTRIDE + (bCol + ks * 16) * 2;
                uint32_t r0, r1, r2, r3;
                LDSM4(r0, r1, r2, r3, bd);
                bh[g * 2][0] = r0; bh[g * 2][1] = r1;
                bh[g * 2 + 1][0] = r2; bh[g * 2 + 1][1] = r3;
            }
#pragma unroll
            for (int mf = 0; mf < 2; mf++)
#pragma unroll
                for (int nf = 0; nf < 4; nf++)
                    MMAH(acc[mf][nf], aw[mf], bh[nf]);
        }

        if (i + 1 < NCH) {
            CP_WAIT0();                 // A(i+1) landed
            stsB((i + 1) & 1, bReg);
        }
        __syncthreads();
    }

    // ---------------- epilogue ----------------
    const int mB = rowBase + wm * 32 + (lane >> 2);
    const int nB0 = colBase + wn * 32 + (lane & 3) * 2;
#pragma unroll
    for (int mf = 0; mf < 2; mf++) {
#pragma unroll
        for (int h = 0; h < 2; h++) {          // row halves (+0 / +8)
            int m = mB + mf * 16 + h * 8;
#pragma unroll
            for (int nf = 0; nf < 4; nf++) {
                int col = nB0 + nf * 8;
                float v0 = acc[mf][nf][2 * h];
                float v1 = acc[mf][nf][2 * h + 1];
                if (!GATHER) {
                    v0 += d_bias2[m * Vv + (col % Vv)];
                    v1 += d_bias2[m * Vv + ((col + 1) % Vv)];
                    uint32_t pk = (uint32_t)__half_as_ushort(__float2half_rn(v0)) |
                                  ((uint32_t)__half_as_ushort(__float2half_rn(v1)) << 16);
                    *(uint32_t*)(d_yP + (size_t)m * COLS + col) = pk;
                } else {
                    float bi = btcn[m];
                    float2 f = make_float2(v0 + bi, v1 + bi);
                    *(float2*)(d_z + (size_t)m * COLS + col) = f;
                }
            }
        }
    }
}

// ---------------------------------------------------------------------------
// BN statistics (deterministic, one block per channel)
// ---------------------------------------------------------------------------
__global__ void bnstats_kernel(const float* __restrict__ gamma,
                               const float* __restrict__ beta)
{
    int d = blockIdx.x;
    const float* zr = d_z + (size_t)d * COLS;
    float s = 0.f, sq = 0.f;
    for (int i = threadIdx.x; i < COLS; i += 256) {
        float v = zr[i];
        s  += v;
        sq += v * v;
    }
    __shared__ float sh1[256], sh2[256];
    sh1[threadIdx.x] = s;
    sh2[threadIdx.x] = sq;
    __syncthreads();
    for (int o = 128; o > 0; o >>= 1) {
        if (threadIdx.x < o) {
            sh1[threadIdx.x] += sh1[threadIdx.x + o];
            sh2[threadIdx.x] += sh2[threadIdx.x + o];
        }
        __syncthreads();
    }
    if (threadIdx.x == 0) {
        float mean = sh1[0] * (1.0f / COLS);
        float var  = sh2[0] * (1.0f / COLS) - mean * mean;
        float r    = rsqrtf(var + 1e-5f);
        d_scale[d] = gamma[d] * r;
        d_shift[d] = beta[d] - gamma[d] * mean * r;
    }
}

// ---------------------------------------------------------------------------
// Finalize: BN apply + residual + ReLU, transpose [d][n,t,v] -> [n][d][t][v]
// ---------------------------------------------------------------------------
__global__ void finalize_kernel(const float* __restrict__ x,
                                float* __restrict__ out)
{
    int e = blockIdx.x * 256 + threadIdx.x;
    int n = e / (Dd * TV);
    int r = e % (Dd * TV);
    int d = r / TV;
    int s = r % TV;
    float z = d_z[(size_t)d * COLS + n * TV + s];
    float v = fmaf(d_scale[d], z, d_shift[d]) + x[e];
    out[e] = fmaxf(v, 0.f);
}

// ---------------------------------------------------------------------------
extern "C" void kernel_launch(void* const* d_in, const int* in_sizes, int n_in,
                              void* d_out, int out_size)
{
    const float* x     = (const float*)d_in[0];
    const float* A     = (const float*)d_in[1];
    const float* W_gcn = (const float*)d_in[2];
    const float* b_gcn = (const float*)d_in[3];
    const float* W_tcn = (const float*)d_in[4];
    const float* b_tcn = (const float*)d_in[5];
    const float* gamma = (const float*)d_in[6];
    const float* beta  = (const float*)d_in[7];
    float* out = (float*)d_out;

    cudaFuncSetAttribute(mma_gemm<false>, cudaFuncAttributeMaxDynamicSharedMemorySize, SMEM_DYN);
    cudaFuncSetAttribute(mma_gemm<true>,  cudaFuncAttributeMaxDynamicSharedMemorySize, SMEM_DYN);

    prep_kernel<<<(2 * NCH2 * 8192 + 255) / 256, 256>>>(W_gcn, b_gcn, W_tcn, A);
    stageA_kernel<<<(Nn * Cc * Tt + 255) / 256, 256>>>(x, A);

    mma_gemm<false><<<dim3(2, 400), 512, SMEM_DYN>>>(nullptr);
    mma_gemm<true><<<dim3(2, 400), 512, SMEM_DYN>>>(b_tcn);

    bnstats_kernel<<<Dd, 256>>>(gamma, beta);
    finalize_kernel<<<(Nn * Dd * TV) / 256, 256>>>(x, out);
}